// round 11
// baseline (speedup 1.0000x reference)
#include <cuda_runtime.h>
#include <cuda_fp16.h>
#include <cstdint>

#define SEQ 512
#define DIN 512
#define MEM 256
#define HID 512
#define NBATCH 64
#define URPAD 640

#define RSB 144                  // row stride bytes: 64 fp16 = 128 B + 16 pad
#define TILEB (128 * RSB)        // 18432 B
#define BUFB (2 * TILEB)         // A, B tiles
#define URS_OFF (2 * BUFB)
#define SMEM_DYN (2 * BUFB + 1280)

#define CHAIN_GRID 256
#define XS_PITCH 260

// ---------------- static device scratch ----------------
__device__ __align__(16) __half g_xh[NBATCH * SEQ * DIN];
__device__ __align__(16) __half g_urh[NBATCH * URPAD];
__device__ __align__(16) __half g_wht[HID * DIN];    // Wht[j][k] = Wh[256+k][j]
__device__ __align__(16) __half g_gt[HID * SEQ];     // Gt[j][d] = G[d][j]
__device__ float g_Ht[SEQ * MEM];
__device__ float g_AT[2][MEM * MEM];
__device__ unsigned g_count;   // zero at load; reset by k_main tail each run
__device__ unsigned g_epoch;

// ---------------- helpers ----------------
__device__ __forceinline__ uint32_t smem_to_u32(const void* p) {
    uint32_t a;
    asm("{ .reg .u64 t; cvta.to.shared.u64 t, %1; cvt.u32.u64 %0, t; }" : "=r"(a) : "l"(p));
    return a;
}
__device__ __forceinline__ void cp16(uint32_t dst, const void* src) {
    asm volatile("cp.async.cg.shared.global [%0], [%1], 16;" :: "r"(dst), "l"(src));
}
#define CP_COMMIT() asm volatile("cp.async.commit_group;" ::: "memory")
#define CP_WAIT0()  asm volatile("cp.async.wait_group 0;" ::: "memory")
#define CP_WAIT1()  asm volatile("cp.async.wait_group 1;" ::: "memory")

__device__ __forceinline__ void ldsm4(uint32_t r[4], uint32_t addr) {
    asm volatile("ldmatrix.sync.aligned.m8n8.x4.shared.b16 {%0,%1,%2,%3}, [%4];"
                 : "=r"(r[0]), "=r"(r[1]), "=r"(r[2]), "=r"(r[3]) : "r"(addr));
}
__device__ __forceinline__ void mma_f16(float* c, const uint32_t* a, const uint32_t* b) {
    asm volatile(
        "mma.sync.aligned.m16n8k16.row.col.f32.f16.f16.f32 "
        "{%0,%1,%2,%3}, {%4,%5,%6,%7}, {%8,%9}, {%0,%1,%2,%3};"
        : "+f"(c[0]), "+f"(c[1]), "+f"(c[2]), "+f"(c[3])
        : "r"(a[0]), "r"(a[1]), "r"(a[2]), "r"(a[3]), "r"(b[0]), "r"(b[1]));
}

// grid barrier among chain blocks: arrive via atomic, wait via acquire-load poll
__device__ __forceinline__ void grid_barrier(int bar) {
    __threadfence();
    __syncthreads();
    if (threadIdx.x == 0) {
        unsigned my = atomicAdd(&g_count, 1u);
        if (my == (unsigned)(CHAIN_GRID * bar - 1)) {
            atomicAdd(&g_epoch, 1u);
        } else {
            while (true) {
                unsigned e;
                asm volatile("ld.global.acquire.gpu.b32 %0, [%1];" : "=r"(e) : "l"(&g_epoch));
                if (e >= (unsigned)bar) break;
                __nanosleep(64);
            }
        }
    }
    __syncthreads();
}

// ---------------- k_ux: u = relu(x@Wu+b) + fp16 x, one pass ----------------
__global__ __launch_bounds__(256) void k_ux(const float* __restrict__ x,
                                            const float* __restrict__ wu,
                                            const float* __restrict__ wub) {
    int row = blockIdx.x * 8 + (threadIdx.x >> 5);   // [0, 32768)
    int lane = threadIdx.x & 31;
    const float4* xr = (const float4*)(x + (size_t)row * DIN);
    const float4* wr = (const float4*)wu;
    float s = 0.f;
#pragma unroll
    for (int i = 0; i < 4; i++) {
        float4 v = xr[lane + 32 * i];
        float4 w = wr[lane + 32 * i];
        s += v.x * w.x + v.y * w.y + v.z * w.z + v.w * w.w;
        size_t off = (size_t)row * DIN + (lane + 32 * i) * 4;
        __half2 ha = {__float2half(v.x), __float2half(v.y)};
        __half2 hb = {__float2half(v.z), __float2half(v.w)};
        *(__half2*)(g_xh + off) = ha; *(__half2*)(g_xh + off + 2) = hb;
    }
#pragma unroll
    for (int o = 16; o; o >>= 1) s += __shfl_xor_sync(0xffffffffu, s, o);
    if (lane == 0) {
        float u = fmaxf(s + wub[0], 0.f);
        int b = row >> 9, t = row & 511;
        g_urh[b * URPAD + (511 - t)] = __float2half(u);
        if (t < 128) g_urh[b * URPAD + 512 + t] = __float2half(0.f);
    }
}

// ---------------- k_wt: transpose Wh_x -> fp16 ----------------
__global__ __launch_bounds__(256) void k_wt(const float* __restrict__ Wh) {
    __shared__ float tile[32][33];
    int kb = blockIdx.x, jb = blockIdx.y;
    int tx = threadIdx.x & 31, ty = threadIdx.x >> 5;
    for (int yy = ty; yy < 32; yy += 8)
        tile[yy][tx] = Wh[(size_t)(MEM + kb * 32 + yy) * HID + jb * 32 + tx];
    __syncthreads();
    for (int yy = ty; yy < 32; yy += 8) {
        float v = tile[tx][yy];
        int j = jb * 32 + yy, k = kb * 32 + tx;
        g_wht[(size_t)j * DIN + k] = __float2half(v);
    }
}

// ---------------- k_chain: A^T init + 9 doubling rounds + G, 16x16 tiles ----------------
__global__ __launch_bounds__(256) void k_chain(const float* __restrict__ Wh,
                                               const float* __restrict__ A,
                                               const float* __restrict__ Bv) {
    __shared__ float Xs[16 * XS_PITCH];
    __shared__ float Bs[256 * 16];
    const int bid = blockIdx.x, tid = threadIdx.x;
    const int ty = tid >> 4, tx = tid & 15;

    // init: block b writes A^T column b; block 0 also Ht[0]=B
    g_AT[0][(size_t)bid * MEM + tid] = A[(size_t)tid * MEM + bid];
    if (bid == 0) g_Ht[tid] = Bv[tid];
    grid_barrier(1);

    for (int r = 0; r <= 8; r++) {
        int n = 1 << r;
        int sel = r & 1;
        int nsq = (r < 8) ? 256 : 0;             // 16x16 squaring tiles
        int nrt = (n + 15) / 16;
        int ntiles = nsq + nrt * 16;
        const float* __restrict__ ATin = g_AT[sel];
        for (int t = bid; t < ntiles; t += CHAIN_GRID) {
            const float* Amat; float* Cmat; int rows, tr, tc;
            if (t < nsq) { Amat = ATin; Cmat = g_AT[sel ^ 1]; rows = MEM; tr = t >> 4; tc = t & 15; }
            else { int te = t - nsq; Amat = g_Ht; Cmat = g_Ht + (size_t)n * MEM; rows = n; tr = te >> 4; tc = te & 15; }
            int r0 = tr * 16, c0 = tc * 16;
            __syncthreads();
            for (int q = tid; q < 1024; q += 256) {
                int row = q >> 6, c4 = (q & 63) * 4;
                float4 v = make_float4(0.f, 0.f, 0.f, 0.f);
                if (r0 + row < rows) v = *(const float4*)(Amat + (size_t)(r0 + row) * MEM + c4);
                *(float4*)&Xs[row * XS_PITCH + c4] = v;
                int brow = q >> 2, bc4 = (q & 3) * 4;
                *(float4*)&Bs[brow * 16 + bc4] = *(const float4*)(ATin + (size_t)brow * MEM + c0 + bc4);
            }
            __syncthreads();
            float acc = 0.f;
#pragma unroll 16
            for (int k = 0; k < MEM; k++)
                acc = fmaf(Xs[ty * XS_PITCH + k], Bs[k * 16 + tx], acc);
            if (r0 + ty < rows) Cmat[(size_t)(r0 + ty) * MEM + c0 + tx] = acc;
        }
        grid_barrier(r + 2);
    }

    // G phase: G = Ht @ Wh_m -> gt[j][d] fp16 (1024 tiles of 16x16)
    for (int t = bid; t < 1024; t += CHAIN_GRID) {
        int tr = t >> 5, tc = t & 31;
        int d0 = tr * 16, j0 = tc * 16;
        __syncthreads();
        for (int q = tid; q < 1024; q += 256) {
            int row = q >> 6, c4 = (q & 63) * 4;
            *(float4*)&Xs[row * XS_PITCH + c4] = *(const float4*)(g_Ht + (size_t)(d0 + row) * MEM + c4);
            int brow = q >> 2, bc4 = (q & 3) * 4;
            *(float4*)&Bs[brow * 16 + bc4] = *(const float4*)(Wh + (size_t)brow * HID + j0 + bc4);
        }
        __syncthreads();
        float acc = 0.f;
#pragma unroll 16
        for (int k = 0; k < MEM; k++)
            acc = fmaf(Xs[ty * XS_PITCH + k], Bs[k * 16 + tx], acc);
        g_gt[(size_t)(j0 + tx) * SEQ + d0 + ty] = __float2half(acc);
    }
}

// ---------------- k_main: single-product fp16 fused GEMM, K=64 chunks ----------------
__device__ __forceinline__ void cp_tile64(uint32_t sdst, const __half* __restrict__ g,
                                          int stride, int tid) {
#pragma unroll
    for (int it = 0; it < 4; it++) {
        int q = tid + it * 256;
        int row = q >> 3, ch = q & 7;
        cp16(sdst + row * RSB + ch * 16, g + (size_t)row * stride + ch * 8);
    }
}

__global__ __launch_bounds__(256, 2) void k_main(const float* __restrict__ Whb,
                                                 float* __restrict__ out, int write_hn) {
    extern __shared__ __align__(128) char smem[];
    const int b = blockIdx.z;
    const int t0 = blockIdx.y * 128;
    const int j0 = blockIdx.x * 128;
    const int tid = threadIdx.x;
    const int lane = tid & 31;
    const int warp_m = (tid >> 5) & 1;
    const int warp_n = tid >> 6;
    const uint32_t sbase = smem_to_u32(smem);

    {
        const uint32_t* gh = (const uint32_t*)(g_urh + (size_t)b * URPAD);
        uint32_t* sh = (uint32_t*)(smem + URS_OFF);
        for (int q = tid; q < 320; q += 256) sh[q] = gh[q];
    }
    __syncthreads();
    const uint32_t* ursh32 = (const uint32_t*)(smem + URS_OFF);

    const __half* xh = g_xh + ((size_t)(b * SEQ + t0)) * DIN;
    const __half* wt = g_wht + (size_t)j0 * DIN;
    const __half* gt = g_gt + (size_t)j0 * SEQ;

    const int nchunks = 10 + 2 * blockIdx.y;

    auto fill = [&](int i, int p) {
        uint32_t sb = sbase + p * BUFB;
        char* sc = smem + p * BUFB;
        if (i < 8) {
            int k0 = i * 64;
            cp_tile64(sb,         xh + k0, DIN, tid);
            cp_tile64(sb + TILEB, wt + k0, DIN, tid);
        } else {
            int d0 = (i - 8) * 64;
            cp_tile64(sb + TILEB, gt + d0, SEQ, tid);
            int r = tid >> 1, hf = tid & 1;
            int s0 = 511 - (t0 + r) + d0 + hf * 32;
            int base = s0 >> 1, par = s0 & 1;
            uint32_t w[16];
            uint32_t w0 = ursh32[base];
#pragma unroll
            for (int c = 0; c < 16; c++) {
                uint32_t w1 = ursh32[base + c + 1];
                w[c] = par ? __byte_perm(w0, w1, 0x5432) : w0;
                w0 = w1;
            }
#pragma unroll
            for (int q = 0; q < 4; q++)
                *(uint4*)(sc + r * RSB + hf * 64 + q * 16) =
                    make_uint4(w[q * 4], w[q * 4 + 1], w[q * 4 + 2], w[q * 4 + 3]);
        }
    };

    float acc[4][4][4];
#pragma unroll
    for (int mi = 0; mi < 4; mi++)
#pragma unroll
        for (int ni = 0; ni < 4; ni++)
#pragma unroll
            for (int e = 0; e < 4; e++) acc[mi][ni][e] = 0.f;

    fill(0, 0);
    CP_COMMIT();

    const uint32_t a_base_off = (warp_m * 64 + (lane & 15)) * RSB + ((lane >> 4) << 4);
    const uint32_t b_base_off = TILEB + (warp_n * 32 + (lane & 15)) * RSB + ((lane >> 4) << 4);

    for (int i = 0; i < nchunks; i++) {
        int p = i & 1;
        if (i + 1 < nchunks) { fill(i + 1, p ^ 1); CP_COMMIT(); CP_WAIT1(); }
        else CP_WAIT0();
        __syncthreads();

        uint32_t base = sbase + p * BUFB;
#pragma unroll
        for (int ks = 0; ks < 4; ks++) {
            uint32_t bh[4][2];
            {
                uint32_t r[4];
                uint32_t baddr = base + b_base_off + ks * 32;
                ldsm4(r, baddr);
                bh[0][0] = r[0]; bh[0][1] = r[2];
                bh[1][0] = r[1]; bh[1][1] = r[3];
                ldsm4(r, baddr + 16 * RSB);
                bh[2][0] = r[0]; bh[2][1] = r[2];
                bh[3][0] = r[1]; bh[3][1] = r[3];
            }
            uint32_t a[4][4];
            uint32_t aaddr = base + a_base_off + ks * 32;
#pragma unroll
            for (int mi = 0; mi < 4; mi++) ldsm4(a[mi], aaddr + mi * 16 * RSB);
#pragma unroll
            for (int mi = 0; mi < 4; mi++)
#pragma unroll
                for (int ni = 0; ni < 4; ni++)
                    mma_f16(acc[mi][ni], a[mi], bh[ni]);
        }
        __syncthreads();
    }

    // ---- epilogue ----
    const int g4 = lane >> 2, t4 = lane & 3;
    const size_t HN_BASE = (size_t)NBATCH * SEQ * HID;
    float2 bias[4];
#pragma unroll
    for (int ni = 0; ni < 4; ni++)
        bias[ni] = *(const float2*)(Whb + j0 + warp_n * 32 + ni * 8 + t4 * 2);
#pragma unroll
    for (int mi = 0; mi < 4; mi++) {
        int ta = t0 + warp_m * 64 + mi * 16 + g4;
        int tb = ta + 8;
        size_t rowa = ((size_t)b * SEQ + ta) * HID;
        size_t rowb = ((size_t)b * SEQ + tb) * HID;
#pragma unroll
        for (int ni = 0; ni < 4; ni++) {
            int j = j0 + warp_n * 32 + ni * 8 + t4 * 2;
            float2 v0, v1;
            v0.x = fmaxf(acc[mi][ni][0] + bias[ni].x, 0.f);
            v0.y = fmaxf(acc[mi][ni][1] + bias[ni].y, 0.f);
            v1.x = fmaxf(acc[mi][ni][2] + bias[ni].x, 0.f);
            v1.y = fmaxf(acc[mi][ni][3] + bias[ni].y, 0.f);
            *(float2*)(out + rowa + j) = v0;
            *(float2*)(out + rowb + j) = v1;
            if (write_hn && tb == SEQ - 1)
                *(float2*)(out + HN_BASE + (size_t)b * HID + j) = v1;
        }
    }

    // reset chain-barrier state for the next replay (zero at load; zeroed after
    // every k_main so every launch sequence sees identical state)
    if (blockIdx.x == 0 && blockIdx.y == 0 && blockIdx.z == 0 && tid == 0) {
        g_count = 0;
        g_epoch = 0;
    }
}

// ---------------- launch ----------------
extern "C" void kernel_launch(void* const* d_in, const int* in_sizes, int n_in,
                              void* d_out, int out_size) {
    const float* x    = (const float*)d_in[0];
    const float* Wu_w = (const float*)d_in[1];
    const float* Wu_b = (const float*)d_in[2];
    const float* Wh_w = (const float*)d_in[3];
    const float* Wh_b = (const float*)d_in[4];
    const float* A    = (const float*)d_in[5];
    const float* B    = (const float*)d_in[6];
    float* out = (float*)d_out;

    int write_hn = (out_size >= NBATCH * SEQ * HID + NBATCH * HID) ? 1 : 0;

    static cudaStream_t s2 = nullptr;
    static cudaEvent_t evFork = nullptr, evJoin = nullptr;
    static int inited = 0;
    if (!inited) {
        cudaFuncSetAttribute(k_main, cudaFuncAttributeMaxDynamicSharedMemorySize, SMEM_DYN);
        cudaStreamCreateWithFlags(&s2, cudaStreamNonBlocking);
        cudaEventCreateWithFlags(&evFork, cudaEventDisableTiming);
        cudaEventCreateWithFlags(&evJoin, cudaEventDisableTiming);
        inited = 1;
    }

    // fork: chain on the main (capture) stream, ux+wt on s2, join before k_main
    cudaEventRecord(evFork, 0);
    cudaStreamWaitEvent(s2, evFork, 0);
    k_chain<<<CHAIN_GRID, 256>>>(Wh_w, A, B);
    k_ux<<<NBATCH * SEQ / 8, 256, 0, s2>>>(x, Wu_w, Wu_b);
    k_wt<<<dim3(16, 16), 256, 0, s2>>>(Wh_w);
    cudaEventRecord(evJoin, s2);
    cudaStreamWaitEvent(0, evJoin, 0);
    k_main<<<dim3(HID / 128, SEQ / 128, NBATCH), 256, SMEM_DYN>>>(Wh_b, out, write_hn);
}